// round 5
// baseline (speedup 1.0000x reference)
#include <cuda_runtime.h>

#define T_ 1024
#define B_ 256
#define D_ 64
#define H_ 128
#define ROWS (T_*B_)

// Scratch (static __device__ arrays per allocation rules).
// g_feat is reused as Z (the tanh(S W_h^T + b_h) buffer) after K1b consumes it.
__device__ float g_feat[ROWS * H_];
__device__ float g_U[ROWS * H_];
__device__ float g_S[ROWS * H_];

// ---------------- packed fp32x2 helpers (Blackwell FFMA2 path) ----------------
static __device__ __forceinline__ unsigned long long pack2(float x, float y) {
    unsigned long long r;
    asm("mov.b64 %0, {%1, %2};" : "=l"(r) : "f"(x), "f"(y));
    return r;
}
static __device__ __forceinline__ void unpack2(unsigned long long v, float& x, float& y) {
    asm("mov.b64 {%0, %1}, %2;" : "=f"(x), "=f"(y) : "l"(v));
}
static __device__ __forceinline__ unsigned long long fma2(unsigned long long a,
                                                          unsigned long long b,
                                                          unsigned long long c) {
    unsigned long long d;
    asm("fma.rn.f32x2 %0, %1, %2, %3;" : "=l"(d) : "l"(a), "l"(b), "l"(c));
    return d;
}

// tanh(x) = 1 - 2/(exp(2x)+1); MUFU.EX2 + MUFU.RCP, ~1e-6 error, handles +-inf.
static __device__ __forceinline__ float fast_tanh(float x) {
    float e = __expf(2.0f * x);
    return 1.0f - __fdividef(2.0f, e + 1.0f);
}

// ---------------- generic row-GEMM: out[row][n] = act(in[row][:] . W[n][:] + b) ----------
// One row per thread; 64 output columns per CTA (blockIdx.y selects the column block).
// W block staged in SMEM k-major so inner loads are warp-uniform broadcasts (LDS.128).
template <int K, bool TANH, bool BIAS2>
__global__ void __launch_bounds__(256) rowgemm64(const float* __restrict__ in,
                                                 const float* __restrict__ W,
                                                 const float* __restrict__ b1,
                                                 const float* __restrict__ b2,
                                                 float* __restrict__ out,
                                                 int N_total) {
    __shared__ __align__(16) float Ws[K * 64];  // Ws[k*64 + nl]
    __shared__ float sb[64];

    const int nbase = blockIdx.y * 64;
    for (int i = threadIdx.x; i < 64 * K; i += 256) {
        int nl = i / K;
        int k  = i - nl * K;
        Ws[k * 64 + nl] = W[(size_t)(nbase + nl) * K + k];
    }
    if (threadIdx.x < 64) {
        float bb = b1[nbase + threadIdx.x];
        if (BIAS2) bb += b2[nbase + threadIdx.x];
        sb[threadIdx.x] = bb;
    }
    __syncthreads();

    const int row = blockIdx.x * 256 + threadIdx.x;
    const float4* xin = (const float4*)(in + (size_t)row * K);

    unsigned long long acc[32];
#pragma unroll
    for (int i = 0; i < 32; ++i) acc[i] = 0ull;

#pragma unroll 4
    for (int kk = 0; kk < K / 4; ++kk) {
        float4 xv = xin[kk];
#pragma unroll
        for (int c = 0; c < 4; ++c) {
            float a = (c == 0) ? xv.x : (c == 1) ? xv.y : (c == 2) ? xv.z : xv.w;
            unsigned long long a2 = pack2(a, a);
            const ulonglong2* wv = (const ulonglong2*)(Ws + (kk * 4 + c) * 64);
#pragma unroll
            for (int n4 = 0; n4 < 16; ++n4) {
                ulonglong2 w = wv[n4];
                acc[2 * n4]     = fma2(w.x, a2, acc[2 * n4]);
                acc[2 * n4 + 1] = fma2(w.y, a2, acc[2 * n4 + 1]);
            }
        }
    }

    float* orow = out + (size_t)row * N_total + nbase;
#pragma unroll
    for (int n4 = 0; n4 < 16; ++n4) {
        float x0, x1, x2, x3;
        unpack2(acc[2 * n4], x0, x1);
        unpack2(acc[2 * n4 + 1], x2, x3);
        float4 o;
        o.x = x0 + sb[4 * n4 + 0];
        o.y = x1 + sb[4 * n4 + 1];
        o.z = x2 + sb[4 * n4 + 2];
        o.w = x3 + sb[4 * n4 + 3];
        if (TANH) {
            o.x = fast_tanh(o.x);
            o.y = fast_tanh(o.y);
            o.z = fast_tanh(o.z);
            o.w = fast_tanh(o.w);
        }
        *(float4*)(orow + 4 * n4) = o;
    }
}

// ---------------- sequential recurrence: per-batch-row independent scan ----------------
// S[0][b][:] = 0;  S[t+1][b][j] = tanh(U[t][b][j] + sum_k S[t][b][k] * W_hh[j][k])
// One CTA per batch row, thread j owns W_hh row j in 128 registers; h double-buffered in SMEM.
__global__ void __launch_bounds__(128) rnn_scan(const float* __restrict__ U,
                                                const float* __restrict__ W_hh,
                                                float* __restrict__ S) {
    const int b = blockIdx.x;
    const int j = threadIdx.x;
    __shared__ __align__(16) float hbuf[2][H_];

    unsigned long long w2[64];
    const float4* wr = (const float4*)(W_hh + (size_t)j * H_);
#pragma unroll
    for (int i = 0; i < 32; ++i) {
        float4 v = wr[i];
        w2[2 * i]     = pack2(v.x, v.y);
        w2[2 * i + 1] = pack2(v.z, v.w);
    }

    hbuf[0][j] = 0.0f;
    S[(size_t)b * H_ + j] = 0.0f;  // S[t=0] = 0
    __syncthreads();

    const float* Ub = U + (size_t)b * H_ + j;  // +t*B_*H_ per step
    float u0 = Ub[0];
    float u1 = Ub[(size_t)B_ * H_];
    int cur = 0;

#pragma unroll 1
    for (int t = 0; t < T_ - 1; ++t) {
        // prefetch U two steps ahead (hide DRAM/L2 latency behind the dot product)
        float u2 = 0.0f;
        if (t + 2 <= T_ - 2) u2 = Ub[(size_t)(t + 2) * B_ * H_];

        const ulonglong2* hv = (const ulonglong2*)hbuf[cur];
        unsigned long long accA = 0ull, accB = 0ull;
#pragma unroll
        for (int i = 0; i < 32; ++i) {
            ulonglong2 hh = hv[i];
            accA = fma2(w2[2 * i], hh.x, accA);
            accB = fma2(w2[2 * i + 1], hh.y, accB);
        }
        float a0, a1, c0, c1;
        unpack2(accA, a0, a1);
        unpack2(accB, c0, c1);
        float hnew = fast_tanh(u0 + ((a0 + a1) + (c0 + c1)));

        hbuf[cur ^ 1][j] = hnew;
        S[((size_t)(t + 1) * B_ + b) * H_ + j] = hnew;

        u0 = u1;
        u1 = u2;
        cur ^= 1;
        __syncthreads();
    }
}

extern "C" void kernel_launch(void* const* d_in, const int* in_sizes, int n_in,
                              void* d_out, int out_size) {
    const float* x    = (const float*)d_in[0];
    const float* W_x  = (const float*)d_in[1];
    const float* b_x  = (const float*)d_in[2];
    const float* W_ih = (const float*)d_in[3];
    const float* b_ih = (const float*)d_in[4];
    const float* W_hh = (const float*)d_in[5];
    const float* b_hh = (const float*)d_in[6];
    const float* W_h  = (const float*)d_in[7];
    const float* b_h  = (const float*)d_in[8];
    const float* W_g  = (const float*)d_in[9];
    const float* b_g  = (const float*)d_in[10];
    float* y = (float*)d_out;

    float *feat, *U, *S;
    cudaGetSymbolAddress((void**)&feat, g_feat);
    cudaGetSymbolAddress((void**)&U, g_U);
    cudaGetSymbolAddress((void**)&S, g_S);

    // K1a: feat = tanh(x W_x^T + b_x)              [ROWS,64] x [128,64]^T
    rowgemm64<64, true, false><<<dim3(ROWS / 256, 2), 256>>>(x, W_x, b_x, nullptr, feat, H_);
    // K1b: U = feat W_ih^T + b_ih + b_hh           [ROWS,128] x [128,128]^T
    rowgemm64<128, false, true><<<dim3(ROWS / 256, 2), 256>>>(feat, W_ih, b_ih, b_hh, U, H_);
    // K2: sequential scan -> S (pre-update states, S[0]=0)
    rnn_scan<<<B_, 128>>>(U, W_hh, S);
    // K3a: Z = tanh(S W_h^T + b_h)                 (reuses g_feat)
    rowgemm64<128, true, false><<<dim3(ROWS / 256, 2), 256>>>(S, W_h, b_h, nullptr, feat, H_);
    // K3b: y = Z W_g^T + b_g                       [ROWS,128] x [64,128]^T
    rowgemm64<128, false, false><<<dim3(ROWS / 256, 1), 256>>>(feat, W_g, b_g, nullptr, y, D_);
}